// round 6
// baseline (speedup 1.0000x reference)
#include <cuda_runtime.h>
#include <cuda_bf16.h>
#include <cstdint>

#define MAXN 40000
#define NPADROWS (MAXN + 64)
#define MAXE 640000
#define INF 128

// ---------------- device scratch ----------------
__device__ float g_P2[MAXN * 64];       // h @ W2l
__device__ float g_Z2[MAXN * 64];       // h @ W2r + b2
__device__ int g_cnt[MAXN];
__device__ int g_rowptr[MAXN + 1];
__device__ int g_fill[MAXN];
__device__ int g_src[MAXE];
__device__ int g_dst[MAXE];
__device__ int g_col[MAXE];
__device__ int g_scan_sum[64];
__device__ int g_scan_flag[64];
// row-major bf16 pairs (u32 = 2 bf16, low = even k), 64 pairs/row
__device__ uint32_t g_x_hi[NPADROWS * 64];
__device__ uint32_t g_x_lo[NPADROWS * 64];
__device__ uint32_t g_ax_hi[NPADROWS * 64];   // mean_agg(x)
__device__ uint32_t g_ax_lo[NPADROWS * 64];
__device__ uint32_t g_h_hi[NPADROWS * 64];
__device__ uint32_t g_h_lo[NPADROWS * 64];
// weights in MMA B-fragment layout
__device__ uint2 g_Wf1_hi[16 * 16 * 32];   // [W1l;W1r] K=256, N=128: (ntile*16+s)*32+lane
__device__ uint2 g_Wf1_lo[16 * 16 * 32];
__device__ uint2 g_Wf2_hi[16 * 8 * 32];    // [W2l|W2r] K=128, N=128: (ntile*8+s)*32+lane
__device__ uint2 g_Wf2_lo[16 * 8 * 32];

// ---------------- helpers ----------------
__device__ __forceinline__ uint32_t bfpack(__nv_bfloat16 a, __nv_bfloat16 b) {
    return (uint32_t)__bfloat16_as_ushort(a) | ((uint32_t)__bfloat16_as_ushort(b) << 16);
}
__device__ __forceinline__ void split2(float x, float y, uint32_t& hi, uint32_t& lo) {
    __nv_bfloat16 hx = __float2bfloat16_rn(x), hy = __float2bfloat16_rn(y);
    float rx = x - __bfloat162float(hx), ry = y - __bfloat162float(hy);
    hi = bfpack(hx, hy);
    lo = bfpack(__float2bfloat16_rn(rx), __float2bfloat16_rn(ry));
}
__device__ __forceinline__ void mma_bf16(float* d, const uint32_t* a,
                                         uint32_t b0, uint32_t b1) {
    asm volatile(
        "mma.sync.aligned.m16n8k16.row.col.f32.bf16.bf16.f32 "
        "{%0,%1,%2,%3}, {%4,%5,%6,%7}, {%8,%9}, {%0,%1,%2,%3};"
        : "+f"(d[0]), "+f"(d[1]), "+f"(d[2]), "+f"(d[3])
        : "r"(a[0]), "r"(a[1]), "r"(a[2]), "r"(a[3]), "r"(b0), "r"(b1));
}

// ---------------- launch 1: hist + x row-pair split + weight frag pack ----------------
__global__ void k_multi1(const float* __restrict__ x, const void* __restrict__ ei,
                         const float* __restrict__ W1l, const float* __restrict__ W1r,
                         const float* __restrict__ W2l, const float* __restrict__ W2r,
                         int n, int E, int hb, int xb) {
    int b = blockIdx.x;
    int tid = threadIdx.x;
    if (b < hb) {  // edge convert + histogram
        int e = b * 256 + tid;
        if (e >= E) return;
        const long long* p64 = (const long long*)ei;
        bool is64 = true;
#pragma unroll
        for (int j = 0; j < 4; j++) {
            unsigned long long v = (unsigned long long)p64[j];
            if (v >> 32) is64 = false;
        }
        int s, d;
        if (is64) {
            s = (int)p64[e];
            d = (int)p64[(size_t)E + e];
        } else {
            const int* p32 = (const int*)ei;
            s = p32[e];
            d = p32[E + e];
        }
        g_src[e] = s;
        g_dst[e] = d;
        atomicAdd(&g_cnt[d], 1);
        return;
    }
    b -= hb;
    if (b < xb) {  // x -> row-major bf16 pairs, 4 pairs (8 floats) per thread
        int i4 = b * 256 + tid;          // quad-pair index
        int p0 = i4 * 4;                 // first pair
        if (p0 >= n * 64) return;
        float4 v0 = *(const float4*)(x + (size_t)p0 * 2);
        float4 v1 = *(const float4*)(x + (size_t)p0 * 2 + 4);
        uint4 h, l;
        split2(v0.x, v0.y, h.x, l.x);
        split2(v0.z, v0.w, h.y, l.y);
        split2(v1.x, v1.y, h.z, l.z);
        split2(v1.z, v1.w, h.w, l.w);
        *(uint4*)(g_x_hi + p0) = h;
        *(uint4*)(g_x_lo + p0) = l;
        return;
    }
    b -= xb;
    if (b < 32) {  // W1 pack: [W1l;W1r] K=256 N=128, 16 ntiles x 16 s
        int idx = b * 256 + tid;         // (t*16+s)*32+lane
        int lane = idx & 31;
        int s = (idx >> 5) & 15;
        int t = idx >> 9;
        int nn = t * 8 + (lane >> 2);
        int q = lane & 3;
        int p0 = s * 8 + q, p1 = p0 + 4;
        float a0, a1, b0f, b1f;
        if (p0 < 64) {
            a0 = W1l[(2 * p0) * 128 + nn];
            a1 = W1l[(2 * p0 + 1) * 128 + nn];
        } else {
            a0 = W1r[(2 * p0 - 128) * 128 + nn];
            a1 = W1r[(2 * p0 - 127) * 128 + nn];
        }
        if (p1 < 64) {
            b0f = W1l[(2 * p1) * 128 + nn];
            b1f = W1l[(2 * p1 + 1) * 128 + nn];
        } else {
            b0f = W1r[(2 * p1 - 128) * 128 + nn];
            b1f = W1r[(2 * p1 - 127) * 128 + nn];
        }
        uint32_t h0, l0, h1, l1;
        split2(a0, a1, h0, l0);
        split2(b0f, b1f, h1, l1);
        g_Wf1_hi[idx] = make_uint2(h0, h1);
        g_Wf1_lo[idx] = make_uint2(l0, l1);
        return;
    }
    b -= 32;
    {  // W2 pack: [W2l|W2r] K=128 N=128, 16 ntiles x 8 s
        int idx = b * 256 + tid;         // (t*8+s)*32+lane
        if (idx >= 16 * 8 * 32) return;
        int lane = idx & 31;
        int s = (idx >> 5) & 7;
        int t = idx >> 8;
        int nn = t * 8 + (lane >> 2);
        int q = lane & 3;
        const float* W = (nn < 64) ? W2l : W2r;
        int nc = (nn < 64) ? nn : nn - 64;
        int p0 = s * 8 + q, p1 = p0 + 4;
        uint32_t h0, l0, h1, l1;
        split2(W[(2 * p0) * 64 + nc], W[(2 * p0 + 1) * 64 + nc], h0, l0);
        split2(W[(2 * p1) * 64 + nc], W[(2 * p1 + 1) * 64 + nc], h1, l1);
        g_Wf2_hi[idx] = make_uint2(h0, h1);
        g_Wf2_lo[idx] = make_uint2(l0, l1);
    }
}

// ---------------- launch 2: single-pass scan (decoupled lookback) + cnt rezero ----------------
__global__ void k_scan(int n, int nb) {
    __shared__ int wsraw[32];
    __shared__ int wsoff[32];
    __shared__ int stot;
    __shared__ int sbase;
    int b = blockIdx.x, tid = threadIdx.x;
    int lane = tid & 31, w = tid >> 5;
    int i = b * 1024 + tid;
    int v = (i < n) ? g_cnt[i] : 0;
    if (i < n) g_cnt[i] = 0;  // rezero for next replay
    int x = v;
#pragma unroll
    for (int off = 1; off < 32; off <<= 1) {
        int y = __shfl_up_sync(0xffffffffu, x, off);
        if (lane >= off) x += y;
    }
    if (lane == 31) wsraw[w] = x;
    __syncthreads();
    if (w == 0) {
        int t = wsraw[lane];
        int tx = t;
#pragma unroll
        for (int off = 1; off < 32; off <<= 1) {
            int y = __shfl_up_sync(0xffffffffu, tx, off);
            if (lane >= off) tx += y;
        }
        wsoff[lane] = tx - t;
        if (lane == 31) stot = tx;
    }
    __syncthreads();
    if (tid == 0) {
        int base = 0;
        if (b > 0) {
            while (((volatile int*)g_scan_flag)[b - 1] == 0) {}
            __threadfence();
            base = ((volatile int*)g_scan_sum)[b - 1];
        }
        g_scan_sum[b] = base + stot;
        __threadfence();
        ((volatile int*)g_scan_flag)[b] = 1;
        sbase = base;
        if (b == nb - 1) g_rowptr[n] = base + stot;
    }
    __syncthreads();
    int excl = x - v + wsoff[w] + sbase;
    if (i < n) {
        g_rowptr[i] = excl;
        g_fill[i] = excl;
    }
}

// ---------------- launch 3: CSR fill + lookback-flag rezero ----------------
__global__ void k_fill2(int E, int fb) {
    int b = blockIdx.x;
    if (b >= fb) {
        if (threadIdx.x < 64) g_scan_flag[threadIdx.x] = 0;
        return;
    }
    int e = b * 256 + threadIdx.x;
    if (e >= E) return;
    int d = g_dst[e];
    int pos = atomicAdd(&g_fill[d], 1);
    g_col[pos] = g_src[e];
}

// ---------------- launch 4: agg(x) -> bf16 split pairs ----------------
__global__ void k_aggx(const float4* __restrict__ x4, int n) {
    int w = (int)((blockIdx.x * (size_t)blockDim.x + threadIdx.x) >> 5);
    int lane = threadIdx.x & 31;
    if (w >= n) return;
    int s = g_rowptr[w], e = g_rowptr[w + 1];
    float4 acc = make_float4(0.f, 0.f, 0.f, 0.f);
    int j = s;
    for (; j + 4 <= e; j += 4) {
        int c0 = g_col[j], c1 = g_col[j + 1], c2 = g_col[j + 2], c3 = g_col[j + 3];
        float4 v0 = x4[(size_t)c0 * 32 + lane];
        float4 v1 = x4[(size_t)c1 * 32 + lane];
        float4 v2 = x4[(size_t)c2 * 32 + lane];
        float4 v3 = x4[(size_t)c3 * 32 + lane];
        acc.x += (v0.x + v1.x) + (v2.x + v3.x);
        acc.y += (v0.y + v1.y) + (v2.y + v3.y);
        acc.z += (v0.z + v1.z) + (v2.z + v3.z);
        acc.w += (v0.w + v1.w) + (v2.w + v3.w);
    }
    for (; j < e; j++) {
        int c = g_col[j];
        float4 v = x4[(size_t)c * 32 + lane];
        acc.x += v.x; acc.y += v.y; acc.z += v.z; acc.w += v.w;
    }
    int deg = e - s;
    float inv = 1.0f / (float)(deg > 0 ? deg : 1);
    uint32_t h0, l0, h1, l1;
    split2(acc.x * inv, acc.y * inv, h0, l0);
    split2(acc.z * inv, acc.w * inv, h1, l1);
    ((uint2*)(g_ax_hi + (size_t)w * 64))[lane] = make_uint2(h0, h1);
    ((uint2*)(g_ax_lo + (size_t)w * 64))[lane] = make_uint2(l0, l1);
}

// ---------------- launch 5: layer-1 fused GEMM (K=256, N=128) -> h bf16 pairs ----------------
// h = relu([agg(x)|x] @ [W1l;W1r] + b1). 128 threads, 4 warps (2M x 2N), CTA 64x128.
__global__ __launch_bounds__(128) void k_mma1(const float* __restrict__ bias, int n) {
    int tid = threadIdx.x;
    int wid = tid >> 5, lane = tid & 31;
    int q = lane & 3, g = lane >> 2;
    int warpM = wid >> 1, warpN = wid & 1;
    int rbase = blockIdx.x * 64 + warpM * 32 + g;

    float acc[2][8][4];
#pragma unroll
    for (int mt = 0; mt < 2; mt++)
#pragma unroll
        for (int nt = 0; nt < 8; nt++)
#pragma unroll
            for (int c = 0; c < 4; c++) acc[mt][nt][c] = 0.0f;

    const uint32_t* agH = g_ax_hi + (size_t)rbase * 64;
    const uint32_t* agL = g_ax_lo + (size_t)rbase * 64;
    const uint32_t* xH = g_x_hi + (size_t)rbase * 64;
    const uint32_t* xL = g_x_lo + (size_t)rbase * 64;

#pragma unroll 2
    for (int s = 0; s < 16; s++) {
        const uint32_t* pH = (s < 8) ? agH : xH;
        const uint32_t* pL = (s < 8) ? agL : xL;
        int kp = (s & 7) * 8 + q;
        uint32_t Ah[2][4], Al[2][4];
#pragma unroll
        for (int mt = 0; mt < 2; mt++) {
            const uint32_t* ph = pH + mt * 1024 + kp;
            const uint32_t* pl = pL + mt * 1024 + kp;
            Ah[mt][0] = ph[0];
            Ah[mt][1] = ph[512];
            Ah[mt][2] = ph[4];
            Ah[mt][3] = ph[516];
            Al[mt][0] = pl[0];
            Al[mt][1] = pl[512];
            Al[mt][2] = pl[4];
            Al[mt][3] = pl[516];
        }
#pragma unroll
        for (int nt = 0; nt < 8; nt++) {
            int idx = ((warpN * 8 + nt) * 16 + s) * 32 + lane;
            uint2 bh = g_Wf1_hi[idx];
            uint2 bl = g_Wf1_lo[idx];
#pragma unroll
            for (int mt = 0; mt < 2; mt++) {
                mma_bf16(acc[mt][nt], Ah[mt], bh.x, bh.y);
                mma_bf16(acc[mt][nt], Ah[mt], bl.x, bl.y);
                mma_bf16(acc[mt][nt], Al[mt], bh.x, bh.y);
            }
        }
    }

    // epilogue: relu(acc + bias), split to bf16 pairs, store h row-major
#pragma unroll
    for (int mt = 0; mt < 2; mt++) {
        int r0 = rbase + mt * 16;
        int r1 = r0 + 8;
#pragma unroll
        for (int nt = 0; nt < 8; nt++) {
            int col = warpN * 64 + nt * 8 + q * 2;
            int cp = col >> 1;
            float b0 = __ldg(bias + col), b1 = __ldg(bias + col + 1);
            const float* a = acc[mt][nt];
            float v0 = fmaxf(a[0] + b0, 0.f), v1 = fmaxf(a[1] + b1, 0.f);
            float v2 = fmaxf(a[2] + b0, 0.f), v3 = fmaxf(a[3] + b1, 0.f);
            uint32_t h, l;
            if (r0 < n) {
                split2(v0, v1, h, l);
                g_h_hi[(size_t)r0 * 64 + cp] = h;
                g_h_lo[(size_t)r0 * 64 + cp] = l;
            }
            if (r1 < n) {
                split2(v2, v3, h, l);
                g_h_hi[(size_t)r1 * 64 + cp] = h;
                g_h_lo[(size_t)r1 * 64 + cp] = l;
            }
        }
    }
}

// ---------------- launch 6: layer-2 GEMM (K=128, N=128 split 64/64) ----------------
__global__ __launch_bounds__(128) void k_mma2(
    const float* __restrict__ bias, float* __restrict__ outL,
    float* __restrict__ outR, int n) {
    int tid = threadIdx.x;
    int wid = tid >> 5, lane = tid & 31;
    int q = lane & 3, g = lane >> 2;
    int warpM = wid >> 1, warpN = wid & 1;
    int rbase = blockIdx.x * 64 + warpM * 32 + g;

    float acc[2][8][4];
#pragma unroll
    for (int mt = 0; mt < 2; mt++)
#pragma unroll
        for (int nt = 0; nt < 8; nt++)
#pragma unroll
            for (int c = 0; c < 4; c++) acc[mt][nt][c] = 0.0f;

    const uint32_t* aH = g_h_hi + (size_t)rbase * 64;
    const uint32_t* aL = g_h_lo + (size_t)rbase * 64;

#pragma unroll 2
    for (int s = 0; s < 8; s++) {
        int kp = s * 8 + q;
        uint32_t Ah[2][4], Al[2][4];
#pragma unroll
        for (int mt = 0; mt < 2; mt++) {
            const uint32_t* ph = aH + mt * 1024 + kp;
            const uint32_t* pl = aL + mt * 1024 + kp;
            Ah[mt][0] = ph[0];
            Ah[mt][1] = ph[512];
            Ah[mt][2] = ph[4];
            Ah[mt][3] = ph[516];
            Al[mt][0] = pl[0];
            Al[mt][1] = pl[512];
            Al[mt][2] = pl[4];
            Al[mt][3] = pl[516];
        }
#pragma unroll
        for (int nt = 0; nt < 8; nt++) {
            int idx = ((warpN * 8 + nt) * 8 + s) * 32 + lane;
            uint2 bh = g_Wf2_hi[idx];
            uint2 bl = g_Wf2_lo[idx];
#pragma unroll
            for (int mt = 0; mt < 2; mt++) {
                mma_bf16(acc[mt][nt], Ah[mt], bh.x, bh.y);
                mma_bf16(acc[mt][nt], Ah[mt], bl.x, bl.y);
                mma_bf16(acc[mt][nt], Al[mt], bh.x, bh.y);
            }
        }
    }

#pragma unroll
    for (int mt = 0; mt < 2; mt++) {
        int r0 = rbase + mt * 16;
        int r1 = r0 + 8;
#pragma unroll
        for (int nt = 0; nt < 8; nt++) {
            int col = warpN * 64 + nt * 8 + q * 2;
            const float* a = acc[mt][nt];
            if (col < 64) {
                if (r0 < n) *(float2*)(outL + (size_t)r0 * 64 + col) = make_float2(a[0], a[1]);
                if (r1 < n) *(float2*)(outL + (size_t)r1 * 64 + col) = make_float2(a[2], a[3]);
            } else {
                int c = col - 64;
                float b0 = __ldg(bias + c), b1 = __ldg(bias + c + 1);
                if (r0 < n) *(float2*)(outR + (size_t)r0 * 64 + c) = make_float2(a[0] + b0, a[1] + b1);
                if (r1 < n) *(float2*)(outR + (size_t)r1 * 64 + c) = make_float2(a[2] + b0, a[3] + b1);
            }
        }
    }
}

// ---------------- launch 7: final aggregation ----------------
__global__ void k_agg_add_64(const float2* __restrict__ P2,
                             const float2* __restrict__ Z2,
                             float2* __restrict__ out2, int n) {
    int w = (int)((blockIdx.x * (size_t)blockDim.x + threadIdx.x) >> 5);
    int lane = threadIdx.x & 31;
    if (w >= n) return;
    int s = g_rowptr[w], e = g_rowptr[w + 1];
    float2 acc = make_float2(0.f, 0.f);
    int j = s;
    for (; j + 4 <= e; j += 4) {
        int c0 = g_col[j], c1 = g_col[j + 1], c2 = g_col[j + 2], c3 = g_col[j + 3];
        float2 v0 = P2[(size_t)c0 * 32 + lane];
        float2 v1 = P2[(size_t)c1 * 32 + lane];
        float2 v2 = P2[(size_t)c2 * 32 + lane];
        float2 v3 = P2[(size_t)c3 * 32 + lane];
        acc.x += (v0.x + v1.x) + (v2.x + v3.x);
        acc.y += (v0.y + v1.y) + (v2.y + v3.y);
    }
    for (; j < e; j++) {
        int c = g_col[j];
        float2 v = P2[(size_t)c * 32 + lane];
        acc.x += v.x; acc.y += v.y;
    }
    int deg = e - s;
    float inv = 1.0f / (float)(deg > 0 ? deg : 1);
    float2 z = Z2[(size_t)w * 32 + lane];
    float2 r;
    r.x = acc.x * inv + z.x;
    r.y = acc.y * inv + z.y;
    out2[(size_t)w * 32 + lane] = r;
}

// ---------------- launch ----------------
extern "C" void kernel_launch(void* const* d_in, const int* in_sizes, int n_in,
                              void* d_out, int out_size) {
    const float* x = (const float*)d_in[0];
    const void* edge_index = d_in[1];
    const float* W1l = (const float*)d_in[2];
    const float* b1 = (const float*)d_in[3];
    const float* W1r = (const float*)d_in[4];
    const float* W2l = (const float*)d_in[5];
    const float* b2 = (const float*)d_in[6];
    const float* W2r = (const float*)d_in[7];
    float* out = (float*)d_out;

    int N = in_sizes[0] / INF;
    int E = in_sizes[1] / 2;
    if (N > MAXN) N = MAXN;
    if (E > MAXE) E = MAXE;

    float *p_P2, *p_Z2;
    cudaGetSymbolAddress((void**)&p_P2, g_P2);
    cudaGetSymbolAddress((void**)&p_Z2, g_Z2);

    // 1: hist + x split + weight packs (independent work co-scheduled)
    int hb = (E + 255) / 256;
    int xb = (N * 16 + 255) / 256;   // quad-pairs
    k_multi1<<<hb + xb + 32 + 16, 256>>>(x, edge_index, W1l, W1r, W2l, W2r, N, E, hb, xb);

    // 2: one-pass scan (zeroes g_cnt for next replay)
    int nb = (N + 1023) / 1024;
    k_scan<<<nb, 1024>>>(N, nb);

    // 3: CSR fill (+ lookback flag rezero)
    int fb = (E + 255) / 256;
    k_fill2<<<fb + 1, 256>>>(E, fb);

    // 4: agg(x) -> bf16 split
    k_aggx<<<(N * 32 + 255) / 256, 256>>>((const float4*)x, N);

    // 5: layer-1 fused GEMM -> h
    int mblocks = (N + 63) / 64;
    k_mma1<<<mblocks, 128>>>(b1, N);

    // 6: layer-2 GEMM -> P2, Z2
    k_mma2<<<mblocks, 128>>>(b2, p_P2, p_Z2, N);

    // 7: final aggregation -> out
    k_agg_add_64<<<(N * 32 + 255) / 256, 256>>>(
        (const float2*)p_P2, (const float2*)p_Z2, (float2*)out, N);
}